// round 6
// baseline (speedup 1.0000x reference)
#include <cuda_runtime.h>
#include <cuda_bf16.h>

#define EMBED_D   128
#define TWO_D     256
#define NEG_SLOPE 0.01f

__device__ __forceinline__ float4 ldcs4(const float* p) {
    return __ldcs(reinterpret_cast<const float4*>(p));
}

// One warp per row (best-measured variant: 187.1us, DRAM 89.4%, 7.09 TB/s).
// Lane l owns float4 slices:
//   att / concate segment part A: floats [4l .. 4l+3]
//   att / concate segment part B: floats [128+4l .. 128+4l+3]
//   output / neighbors:           floats [4l .. 4l+3] of the 128-wide row
// All 12 global float4 loads are issued before the shuffle-reduction chain so
// the neighbor-row DRAM fetches stay in flight behind the ~500-cycle SHFL
// dependency chain. Streaming hints keep one-pass data from churning L2.
__global__ __launch_bounds__(256) void gat_kernel(
    const int*   __restrict__ node_type,
    const float* __restrict__ c_agg,      // [N,128]
    const float* __restrict__ concate,    // [N,4,256]
    const float* __restrict__ a_agg,      // [N,128]
    const float* __restrict__ p_agg,      // [N,128]
    const float* __restrict__ v_agg,      // [N,128]
    const float* __restrict__ a_att,      // [256]
    const float* __restrict__ p_att,      // [256]
    const float* __restrict__ v_att,      // [256]
    float*       __restrict__ out,        // [N,128]
    int N)
{
    const int lane = threadIdx.x & 31;
    const int row  = (blockIdx.x * blockDim.x + threadIdx.x) >> 5;
    if (row >= N) return;

    // Uniform branch: select attention vector by node type.
    const int nt = *node_type;
    const float* att = (nt == 1) ? a_att : (nt == 2) ? p_att : v_att;

    // att slices in registers (L1/L2-resident after the first warps).
    const float4 attA = *reinterpret_cast<const float4*>(att + 4 * lane);
    const float4 attB = *reinterpret_cast<const float4*>(att + 128 + 4 * lane);

    // ---- issue ALL global loads up front: 8 concate + 4 neighbor float4s ----
    const float* ce_row = concate + (size_t)row * (4 * TWO_D);
    float4 xA[4], xB[4];
#pragma unroll
    for (int k = 0; k < 4; ++k) {
        const float* seg = ce_row + k * TWO_D;
        xA[k] = ldcs4(seg + 4 * lane);
        xB[k] = ldcs4(seg + 128 + 4 * lane);
    }

    const size_t base = (size_t)row * EMBED_D + 4 * lane;
    const float4 xc = ldcs4(c_agg + base);
    const float4 xa = ldcs4(a_agg + base);
    const float4 xp = ldcs4(p_agg + base);
    const float4 xv = ldcs4(v_agg + base);

    // ---- scores: 4 dot products of length 256 ----
    float s[4];
#pragma unroll
    for (int k = 0; k < 4; ++k) {
        float acc;
        acc  = xA[k].x * attA.x;
        acc += xA[k].y * attA.y;
        acc += xA[k].z * attA.z;
        acc += xA[k].w * attA.w;
        acc += xB[k].x * attB.x;
        acc += xB[k].y * attB.y;
        acc += xB[k].z * attB.z;
        acc += xB[k].w * attB.w;
        s[k] = acc;
    }

    // Butterfly reduction: afterwards every lane holds all 4 full dots.
    // Neighbor loads (xc/xa/xp/xv) remain in flight here.
#pragma unroll
    for (int off = 16; off > 0; off >>= 1) {
#pragma unroll
        for (int k = 0; k < 4; ++k)
            s[k] += __shfl_xor_sync(0xffffffffu, s[k], off);
    }

    // LeakyReLU + softmax over the 4 neighbors (redundant per lane).
#pragma unroll
    for (int k = 0; k < 4; ++k)
        s[k] = (s[k] >= 0.0f) ? s[k] : NEG_SLOPE * s[k];

    float m = fmaxf(fmaxf(s[0], s[1]), fmaxf(s[2], s[3]));
    float w0 = __expf(s[0] - m);
    float w1 = __expf(s[1] - m);
    float w2 = __expf(s[2] - m);
    float w3 = __expf(s[3] - m);
    const float inv = 1.0f / (w0 + w1 + w2 + w3);
    w0 *= inv; w1 *= inv; w2 *= inv; w3 *= inv;

    // ---- weighted aggregation of the 4 neighbor rows ----
    float4 o;
    o.x = w0 * xc.x + w1 * xa.x + w2 * xp.x + w3 * xv.x;
    o.y = w0 * xc.y + w1 * xa.y + w2 * xp.y + w3 * xv.y;
    o.z = w0 * xc.z + w1 * xa.z + w2 * xp.z + w3 * xv.z;
    o.w = w0 * xc.w + w1 * xa.w + w2 * xp.w + w3 * xv.w;
    __stcs(reinterpret_cast<float4*>(out + base), o);
}

extern "C" void kernel_launch(void* const* d_in, const int* in_sizes, int n_in,
                              void* d_out, int out_size)
{
    const int*   node_type = (const int*)  d_in[0];
    const float* c_agg     = (const float*)d_in[1];
    const float* concate   = (const float*)d_in[2];
    const float* a_agg     = (const float*)d_in[3];
    const float* p_agg     = (const float*)d_in[4];
    const float* v_agg     = (const float*)d_in[5];
    const float* a_att     = (const float*)d_in[6];
    const float* p_att     = (const float*)d_in[7];
    const float* v_att     = (const float*)d_in[8];
    float* out = (float*)d_out;

    const int N = in_sizes[1] / EMBED_D;   // c_agg_batch is [N,128]

    const int threads = 256;               // 8 warps -> 8 rows per block
    const int rows_per_block = threads / 32;
    const int blocks = (N + rows_per_block - 1) / rows_per_block;
    gat_kernel<<<blocks, threads>>>(node_type, c_agg, concate,
                                    a_agg, p_agg, v_agg,
                                    a_att, p_att, v_att, out, N);
}

// round 8
// speedup vs baseline: 1.0094x; 1.0094x over previous
#include <cuda_runtime.h>
#include <cuda_bf16.h>

#define EMBED_D   128
#define TWO_D     256
#define NEG_SLOPE 0.01f

__device__ __forceinline__ float4 ldcs4(const float* p) {
    return __ldcs(reinterpret_cast<const float4*>(p));
}

// CONVERGED at the HBM roofline: 1.33 GB single-pass traffic / ~7.07 TB/s
// achieved = ~188us. Six structural variants (occ 42-86%, regs 31-64,
// 1-2 rows/warp, smem-staged att) all measured 187-189us at 88-89.4% DRAM.
//
// One warp per row. Lane l owns float4 slices:
//   att / concate segment part A: floats [4l .. 4l+3]
//   att / concate segment part B: floats [128+4l .. 128+4l+3]
//   output / neighbors:           floats [4l .. 4l+3] of the 128-wide row
// All 12 global float4 loads are issued before the shuffle-reduction chain so
// the neighbor-row DRAM fetches stay in flight behind the SHFL dependency
// chain. Streaming hints keep one-pass data from churning L2.
__global__ __launch_bounds__(256) void gat_kernel(
    const int*   __restrict__ node_type,
    const float* __restrict__ c_agg,      // [N,128]
    const float* __restrict__ concate,    // [N,4,256]
    const float* __restrict__ a_agg,      // [N,128]
    const float* __restrict__ p_agg,      // [N,128]
    const float* __restrict__ v_agg,      // [N,128]
    const float* __restrict__ a_att,      // [256]
    const float* __restrict__ p_att,      // [256]
    const float* __restrict__ v_att,      // [256]
    float*       __restrict__ out,        // [N,128]
    int N)
{
    const int lane = threadIdx.x & 31;
    const int row  = (blockIdx.x * blockDim.x + threadIdx.x) >> 5;
    if (row >= N) return;

    // Uniform branch: select attention vector by node type.
    const int nt = *node_type;
    const float* att = (nt == 1) ? a_att : (nt == 2) ? p_att : v_att;

    // att slices in registers (L1/L2-resident after the first warps).
    const float4 attA = *reinterpret_cast<const float4*>(att + 4 * lane);
    const float4 attB = *reinterpret_cast<const float4*>(att + 128 + 4 * lane);

    // ---- issue ALL global loads up front: 8 concate + 4 neighbor float4s ----
    const float* ce_row = concate + (size_t)row * (4 * TWO_D);
    float4 xA[4], xB[4];
#pragma unroll
    for (int k = 0; k < 4; ++k) {
        const float* seg = ce_row + k * TWO_D;
        xA[k] = ldcs4(seg + 4 * lane);
        xB[k] = ldcs4(seg + 128 + 4 * lane);
    }

    const size_t base = (size_t)row * EMBED_D + 4 * lane;
    const float4 xc = ldcs4(c_agg + base);
    const float4 xa = ldcs4(a_agg + base);
    const float4 xp = ldcs4(p_agg + base);
    const float4 xv = ldcs4(v_agg + base);

    // ---- scores: 4 dot products of length 256 ----
    float s[4];
#pragma unroll
    for (int k = 0; k < 4; ++k) {
        float acc;
        acc  = xA[k].x * attA.x;
        acc += xA[k].y * attA.y;
        acc += xA[k].z * attA.z;
        acc += xA[k].w * attA.w;
        acc += xB[k].x * attB.x;
        acc += xB[k].y * attB.y;
        acc += xB[k].z * attB.z;
        acc += xB[k].w * attB.w;
        s[k] = acc;
    }

    // Butterfly reduction: afterwards every lane holds all 4 full dots.
    // Neighbor loads (xc/xa/xp/xv) remain in flight here.
#pragma unroll
    for (int off = 16; off > 0; off >>= 1) {
#pragma unroll
        for (int k = 0; k < 4; ++k)
            s[k] += __shfl_xor_sync(0xffffffffu, s[k], off);
    }

    // LeakyReLU + softmax over the 4 neighbors (redundant per lane).
#pragma unroll
    for (int k = 0; k < 4; ++k)
        s[k] = (s[k] >= 0.0f) ? s[k] : NEG_SLOPE * s[k];

    float m = fmaxf(fmaxf(s[0], s[1]), fmaxf(s[2], s[3]));
    float w0 = __expf(s[0] - m);
    float w1 = __expf(s[1] - m);
    float w2 = __expf(s[2] - m);
    float w3 = __expf(s[3] - m);
    const float inv = 1.0f / (w0 + w1 + w2 + w3);
    w0 *= inv; w1 *= inv; w2 *= inv; w3 *= inv;

    // ---- weighted aggregation of the 4 neighbor rows ----
    float4 o;
    o.x = w0 * xc.x + w1 * xa.x + w2 * xp.x + w3 * xv.x;
    o.y = w0 * xc.y + w1 * xa.y + w2 * xp.y + w3 * xv.y;
    o.z = w0 * xc.z + w1 * xa.z + w2 * xp.z + w3 * xv.z;
    o.w = w0 * xc.w + w1 * xa.w + w2 * xp.w + w3 * xv.w;
    __stcs(reinterpret_cast<float4*>(out + base), o);
}

extern "C" void kernel_launch(void* const* d_in, const int* in_sizes, int n_in,
                              void* d_out, int out_size)
{
    const int*   node_type = (const int*)  d_in[0];
    const float* c_agg     = (const float*)d_in[1];
    const float* concate   = (const float*)d_in[2];
    const float* a_agg     = (const float*)d_in[3];
    const float* p_agg     = (const float*)d_in[4];
    const float* v_agg     = (const float*)d_in[5];
    const float* a_att     = (const float*)d_in[6];
    const float* p_att     = (const float*)d_in[7];
    const float* v_att     = (const float*)d_in[8];
    float* out = (float*)d_out;

    const int N = in_sizes[1] / EMBED_D;   // c_agg_batch is [N,128]

    const int threads = 256;               // 8 warps -> 8 rows per block
    const int rows_per_block = threads / 32;
    const int blocks = (N + rows_per_block - 1) / rows_per_block;
    gat_kernel<<<blocks, threads>>>(node_type, c_agg, concate,
                                    a_agg, p_agg, v_agg,
                                    a_att, p_att, v_att, out, N);
}